// round 8
// baseline (speedup 1.0000x reference)
#include <cuda_runtime.h>
#include <math_constants.h>

// Sparse segment-max pooling, CSR two-pass, edge-streaming pool.
//   features : [N_IN, 32] f32, in_map : [E] i32, out_map : [E] i32 sorted,
//   out : [N_OUT, 32] f32 (empty segments -> 0)
//
// Pool: each warp owns RPW=16 CONSECUTIVE output rows -> one contiguous edge
// range [offsets[row0], offsets[row0+16]). One coalesced lane-load fetches all
// 17 offsets into registers. The warp streams its edges in full 32-wide
// coalesced in_map batches (next batch prefetched), gathers feature rows
// (lane = channel, 128B coalesced) 8-deep pipelined, and folds with a
// warp-uniform boundary walk against the register-resident offsets.
// Each output row stored exactly once (coalesced 128B). No atomics.

#define MAX_NOUT (1 << 18)
#define RPW 16   // output rows per warp (<= 31)

__device__ int g_offsets[MAX_NOUT + 1];

__global__ __launch_bounds__(256)
void build_offsets(const int* __restrict__ out_map, int E, int n_out)
{
    int e = blockIdx.x * blockDim.x + threadIdx.x;
    if (e >= E) return;

    int o = __ldg(&out_map[e]);
    if (o < 0) o = 0;
    if (o >= n_out) o = n_out - 1;

    // prev via warp shuffle: one coalesced load instead of two.
    int prev = __shfl_up_sync(0xffffffffu, o, 1);
    if ((threadIdx.x & 31) == 0)
        prev = (e == 0) ? -1 : min(max(__ldg(&out_map[e - 1]), 0), n_out - 1);

    for (int r = prev + 1; r <= o; r++)
        g_offsets[r] = e;

    if (e == E - 1)
        for (int r = o + 1; r <= n_out; r++)
            g_offsets[r] = E;
}

__global__ __launch_bounds__(256)
void sparse_pool_kernel(const float* __restrict__ features,
                        const int*   __restrict__ in_map,
                        float*       __restrict__ out,
                        int n_out)
{
    const int warp_global = (blockIdx.x * blockDim.x + threadIdx.x) >> 5;
    const int lane = threadIdx.x & 31;
    const int row0 = warp_global * RPW;
    if (row0 >= n_out) return;

    const unsigned FULL = 0xffffffffu;

    // One coalesced load: lane l holds offsets[row0 + l] (l <= RPW used).
    const int off = __ldg(&g_offsets[min(row0 + lane, n_out)]);

    const int nrows      = min(RPW, n_out - row0);
    const int warp_start = __shfl_sync(FULL, off, 0);
    const int warp_end   = __shfl_sync(FULL, off, nrows);

    float m = -CUDART_INF_F;
    int k = 0;                                    // current row within warp
    int start_k = warp_start;
    int end_k   = __shfl_sync(FULL, off, 1);

    // Prime the in_map pipeline (batch 0).
    int base = warp_start;
    int cnt  = min(warp_end - base, 32);          // may be <= 0 (all rows empty)
    int myidx = (cnt > 0 && lane < cnt) ? __ldg(&in_map[base + lane]) : 0;

    while (base < warp_end) {
        // Prefetch next batch's indices (independent of this batch's gathers).
        const int nbase = base + 32;
        const int ncnt  = min(warp_end - nbase, 32);
        int nidx = (ncnt > 0 && lane < ncnt) ? __ldg(&in_map[nbase + lane]) : 0;

        // Process this batch in chunks of 8: issue 8 independent gathers,
        // then fold them with the row-boundary walk (all warp-uniform).
        #pragma unroll
        for (int c = 0; c < 4; c++) {
            const int j0 = c * 8;
            if (j0 >= cnt) break;
            const int jn = min(cnt - j0, 8);

            float f[8];
            #pragma unroll
            for (int j = 0; j < 8; j++) {
                if (j < jn) {
                    int r = __shfl_sync(FULL, myidx, j0 + j);
                    f[j] = __ldg(&features[(size_t)r * 32 + lane]);
                }
            }
            #pragma unroll
            for (int j = 0; j < 8; j++) {
                if (j < jn) {
                    const int e = base + j0 + j;
                    while (e >= end_k) {          // warp-uniform row advance
                        out[(size_t)(row0 + k) * 32 + lane] =
                            (end_k > start_k) ? m : 0.0f;
                        m = -CUDART_INF_F;
                        k++;
                        start_k = end_k;
                        end_k = __shfl_sync(FULL, off, k + 1);
                    }
                    m = fmaxf(m, f[j]);
                }
            }
        }

        base  = nbase;
        cnt   = ncnt;
        myidx = nidx;
    }

    // Flush remaining rows (current row k, then any trailing empty rows).
    while (k < nrows) {
        out[(size_t)(row0 + k) * 32 + lane] = (end_k > start_k) ? m : 0.0f;
        m = -CUDART_INF_F;
        k++;
        start_k = end_k;
        if (k < nrows) end_k = __shfl_sync(FULL, off, k + 1);
    }
}

extern "C" void kernel_launch(void* const* d_in, const int* in_sizes, int n_in,
                              void* d_out, int out_size)
{
    const float* features = (const float*)d_in[0];
    const int*   in_map   = (const int*)d_in[1];
    const int*   out_map  = (const int*)d_in[2];
    float* out = (float*)d_out;

    const int E = in_sizes[1];
    int n_out = out_size / 32;
    if (n_out > MAX_NOUT) n_out = MAX_NOUT;

    {
        const int threads = 256;
        const int blocks = (E + threads - 1) / threads;
        build_offsets<<<blocks, threads>>>(out_map, E, n_out);
    }
    {
        const int threads = 256;  // 8 warps/block
        const int warps = (n_out + RPW - 1) / RPW;
        const int blocks = (warps * 32 + threads - 1) / threads;
        sparse_pool_kernel<<<blocks, threads>>>(features, in_map, out, n_out);
    }
}